// round 3
// baseline (speedup 1.0000x reference)
#include <cuda_runtime.h>
#include <math.h>

// Problem constants
#define NN        512          // feature dim n
#define ROWS      256          // B*S = 2*128
#define BM        32
#define BN        32
#define BK        32
#define NB_GEMM   128          // (ROWS/BM)*(NN/BN) = 8*16
#define NB_FILL   1056         // 128 + 1056 = 1184 = 148 SMs * 8 blocks -> one full wave
#define THREADS   256

#define SAMPLE_ELEMS 131072
#define STD_QUADS    16777216u            // 67108864 floats / 4
#define FILL_STRIDE  (NB_FILL * THREADS)  // 270336

__global__ __launch_bounds__(THREADS, 8)
void gaussian_sampler_fused(const float* __restrict__ x,
                            const float* __restrict__ W,
                            const float* __restrict__ b,
                            const float* __restrict__ eps,
                            float* __restrict__ out)
{
    float* __restrict__ outS = out;                       // sample
    float* __restrict__ outM = out + SAMPLE_ELEMS;        // mu
    float* __restrict__ outD = out + 2 * SAMPLE_ELEMS;    // std_mat

    if (blockIdx.x >= NB_GEMM) {
        // ---------------- FILL ROLE: zero all of std_mat except diag quads ----------------
        const float4 z = make_float4(0.f, 0.f, 0.f, 0.f);
        unsigned q0 = (blockIdx.x - NB_GEMM) * THREADS + threadIdx.x;
        #pragma unroll 4
        for (unsigned q = q0; q < STD_QUADS; q += FILL_STRIDE) {
            unsigned rowAll = q >> 7;         // (b*S+s)*512 + i
            unsigned c4     = q & 127u;       // quad column within 512-wide row
            unsigned i      = rowAll & 511u;  // i within the 512x512 matrix
            if ((i >> 2) != c4) {             // diag quad owned by GEMM role
                __stcs(reinterpret_cast<float4*>(outD) + q, z);
            }
        }
        return;
    }

    // ---------------- GEMM ROLE ----------------
    __shared__ float Xs[BM][BK + 1];
    __shared__ float Wv[BN][BK + 1];
    __shared__ float Wm[BN][BK + 1];

    const int bm   = blockIdx.x >> 4;
    const int bn   = blockIdx.x & 15;
    const int row0 = bm * BM;
    const int n0   = bn * BN;

    const int tid = threadIdx.x;
    const int tx  = tid & 15;
    const int ty  = tid >> 4;
    const int rl  = ty * 2;
    const int nl  = tx * 2;

    const int lr = tid >> 3;
    const int lc = (tid & 7) * 4;

    float av[2][2] = {{0.f,0.f},{0.f,0.f}};
    float am[2][2] = {{0.f,0.f},{0.f,0.f}};

    for (int k0 = 0; k0 < NN; k0 += BK) {
        float4 xv = *reinterpret_cast<const float4*>(&x[(size_t)(row0 + lr) * NN + k0 + lc]);
        Xs[lr][lc + 0] = xv.x; Xs[lr][lc + 1] = xv.y;
        Xs[lr][lc + 2] = xv.z; Xs[lr][lc + 3] = xv.w;

        float4 wv = *reinterpret_cast<const float4*>(&W[(size_t)(n0 + lr) * NN + k0 + lc]);
        Wv[lr][lc + 0] = wv.x; Wv[lr][lc + 1] = wv.y;
        Wv[lr][lc + 2] = wv.z; Wv[lr][lc + 3] = wv.w;

        float4 wm = *reinterpret_cast<const float4*>(&W[(size_t)(512 + n0 + lr) * NN + k0 + lc]);
        Wm[lr][lc + 0] = wm.x; Wm[lr][lc + 1] = wm.y;
        Wm[lr][lc + 2] = wm.z; Wm[lr][lc + 3] = wm.w;

        __syncthreads();

        #pragma unroll
        for (int kk = 0; kk < BK; kk++) {
            float x0 = Xs[rl][kk],     x1 = Xs[rl + 1][kk];
            float v0 = Wv[nl][kk],     v1 = Wv[nl + 1][kk];
            float m0 = Wm[nl][kk],     m1 = Wm[nl + 1][kk];
            av[0][0] += x0 * v0;  av[0][1] += x0 * v1;
            av[1][0] += x1 * v0;  av[1][1] += x1 * v1;
            am[0][0] += x0 * m0;  am[0][1] += x0 * m1;
            am[1][0] += x1 * m0;  am[1][1] += x1 * m1;
        }
        __syncthreads();
    }

    #pragma unroll
    for (int rr = 0; rr < 2; rr++) {
        #pragma unroll
        for (int nn = 0; nn < 2; nn++) {
            const int row = row0 + rl + rr;
            const int n   = n0 + nl + nn;
            float v  = av[rr][nn] + b[n];
            float m  = am[rr][nn] + b[512 + n];
            float sp = (v > 20.f) ? v : log1pf(expf(v));   // softplus, overflow-safe
            const int idx = row * NN + n;
            outM[idx] = m;
            outS[idx] = m + sqrtf(sp) * eps[idx];
            // write the whole diagonal-containing quad: 3 zeros + sp in lane (n&3)
            float4 dq = make_float4(0.f, 0.f, 0.f, 0.f);
            (&dq.x)[n & 3] = sp;
            *reinterpret_cast<float4*>(&outD[(size_t)idx * NN + (n & ~3)]) = dq;
        }
    }
}

extern "C" void kernel_launch(void* const* d_in, const int* in_sizes, int n_in,
                              void* d_out, int out_size)
{
    const float* x   = (const float*)d_in[0];   // (2,128,512)
    const float* W   = (const float*)d_in[1];   // (1024,512)
    const float* b   = (const float*)d_in[2];   // (1024,)
    const float* eps = (const float*)d_in[3];   // (2,128,512)
    float* out = (float*)d_out;

    (void)in_sizes; (void)n_in; (void)out_size;

    gaussian_sampler_fused<<<NB_GEMM + NB_FILL, THREADS>>>(x, W, b, eps, out);
}

// round 4
// speedup vs baseline: 1.1186x; 1.1186x over previous
#include <cuda_runtime.h>
#include <math.h>

// Problem constants
#define NN        512          // feature dim n
#define ROWS      256          // B*S = 2*128
#define BM        32
#define BN        32
#define BK        32
#define NB_GEMM   128          // (ROWS/BM)*(NN/BN) = 8*16
#define THREADS   256

#define SAMPLE_ELEMS 131072
#define STD_BYTES    268435456ull   // 256*512*512 floats * 4B

__global__ __launch_bounds__(THREADS)
void gaussian_sampler_gemm(const float* __restrict__ x,
                           const float* __restrict__ W,
                           const float* __restrict__ b,
                           const float* __restrict__ eps,
                           float* __restrict__ out)
{
    float* __restrict__ outS = out;                       // sample
    float* __restrict__ outM = out + SAMPLE_ELEMS;        // mu
    float* __restrict__ outD = out + 2 * SAMPLE_ELEMS;    // std_mat (pre-zeroed by memset)

    __shared__ float Xs[BM][BK + 1];
    __shared__ float Wv[BN][BK + 1];
    __shared__ float Wm[BN][BK + 1];

    const int bm   = blockIdx.x >> 4;     // 8 row tiles
    const int bn   = blockIdx.x & 15;     // 16 n tiles
    const int row0 = bm * BM;
    const int n0   = bn * BN;

    const int tid = threadIdx.x;
    const int tx  = tid & 15;
    const int ty  = tid >> 4;
    const int rl  = ty * 2;
    const int nl  = tx * 2;

    const int lr = tid >> 3;              // staging row 0..31
    const int lc = (tid & 7) * 4;         // staging float4 col

    float av[2][2] = {{0.f,0.f},{0.f,0.f}};
    float am[2][2] = {{0.f,0.f},{0.f,0.f}};

    for (int k0 = 0; k0 < NN; k0 += BK) {
        float4 xv = *reinterpret_cast<const float4*>(&x[(size_t)(row0 + lr) * NN + k0 + lc]);
        Xs[lr][lc + 0] = xv.x; Xs[lr][lc + 1] = xv.y;
        Xs[lr][lc + 2] = xv.z; Xs[lr][lc + 3] = xv.w;

        float4 wv = *reinterpret_cast<const float4*>(&W[(size_t)(n0 + lr) * NN + k0 + lc]);
        Wv[lr][lc + 0] = wv.x; Wv[lr][lc + 1] = wv.y;
        Wv[lr][lc + 2] = wv.z; Wv[lr][lc + 3] = wv.w;

        float4 wm = *reinterpret_cast<const float4*>(&W[(size_t)(512 + n0 + lr) * NN + k0 + lc]);
        Wm[lr][lc + 0] = wm.x; Wm[lr][lc + 1] = wm.y;
        Wm[lr][lc + 2] = wm.z; Wm[lr][lc + 3] = wm.w;

        __syncthreads();

        #pragma unroll
        for (int kk = 0; kk < BK; kk++) {
            float x0 = Xs[rl][kk],     x1 = Xs[rl + 1][kk];
            float v0 = Wv[nl][kk],     v1 = Wv[nl + 1][kk];
            float m0 = Wm[nl][kk],     m1 = Wm[nl + 1][kk];
            av[0][0] += x0 * v0;  av[0][1] += x0 * v1;
            av[1][0] += x1 * v0;  av[1][1] += x1 * v1;
            am[0][0] += x0 * m0;  am[0][1] += x0 * m1;
            am[1][0] += x1 * m0;  am[1][1] += x1 * m1;
        }
        __syncthreads();
    }

    #pragma unroll
    for (int rr = 0; rr < 2; rr++) {
        #pragma unroll
        for (int nn = 0; nn < 2; nn++) {
            const int row = row0 + rl + rr;
            const int n   = n0 + nl + nn;
            float v  = av[rr][nn] + b[n];
            float m  = am[rr][nn] + b[512 + n];
            float sp = (v > 20.f) ? v : log1pf(expf(v));   // softplus, overflow-safe
            const int idx = row * NN + n;
            outM[idx] = m;
            outS[idx] = m + sqrtf(sp) * eps[idx];
            outD[(size_t)idx * NN + n] = sp;               // diagonal over pre-zeroed std_mat
        }
    }
}

extern "C" void kernel_launch(void* const* d_in, const int* in_sizes, int n_in,
                              void* d_out, int out_size)
{
    const float* x   = (const float*)d_in[0];   // (2,128,512)
    const float* W   = (const float*)d_in[1];   // (1024,512)
    const float* b   = (const float*)d_in[2];   // (1024,)
    const float* eps = (const float*)d_in[3];   // (2,128,512)
    float* out = (float*)d_out;

    (void)in_sizes; (void)n_in; (void)out_size;

    // Node 1: driver-optimized zero-fill of std_mat (graph-capturable memset node)
    cudaMemsetAsync(out + 2 * SAMPLE_ELEMS, 0, STD_BYTES);

    // Node 2: small GEMM writes sample, mu, and the softplus diagonal over the zeros
    gaussian_sampler_gemm<<<NB_GEMM, THREADS>>>(x, W, b, eps, out);
}

// round 5
// speedup vs baseline: 1.1932x; 1.0668x over previous
#include <cuda_runtime.h>
#include <math.h>

// Problem constants
#define NN        512
#define ROWS      256
#define BM        32
#define BN        32
#define BK        32
#define NB_GEMM   128          // 8 row tiles * 16 n tiles
#define NB_FILL   760          // 128 + 760 = 888 = 148 SMs * 6 blocks (42 regs) -> one wave
#define THREADS   256

#define SAMPLE_ELEMS 131072
#define STD_QUADS    16777216u           // 256*512*512 / 4
#define CHUNK_QUADS  2048u               // 256 threads * 8 quads
#define NUM_CHUNKS   8192u               // STD_QUADS / CHUNK_QUADS (exact)

// Scratch for the softplus diagonal values (512 KB static device array)
__device__ float g_diag[SAMPLE_ELEMS];

__global__ __launch_bounds__(THREADS)
void gaussian_sampler_main(const float* __restrict__ x,
                           const float* __restrict__ W,
                           const float* __restrict__ b,
                           const float* __restrict__ eps,
                           float* __restrict__ out)
{
    float* __restrict__ outS = out;                       // sample
    float* __restrict__ outM = out + SAMPLE_ELEMS;        // mu
    float* __restrict__ outD = out + 2 * SAMPLE_ELEMS;    // std_mat

    if (blockIdx.x >= NB_GEMM) {
        // ---------------- FILL ROLE: zero the ENTIRE std_mat, lean store loop ----------------
        const unsigned fb = blockIdx.x - NB_GEMM;
        float4* __restrict__ d4 = reinterpret_cast<float4*>(outD);
        const float4 z = make_float4(0.f, 0.f, 0.f, 0.f);
        for (unsigned c = fb; c < NUM_CHUNKS; c += NB_FILL) {
            float4* p = d4 + (size_t)c * CHUNK_QUADS + threadIdx.x;
            #pragma unroll
            for (int k = 0; k < 8; k++)
                p[k * THREADS] = z;       // STG.128 [R+imm], imm = k*4096B
        }
        return;
    }

    // ---------------- GEMM ROLE (hidden under the fill) ----------------
    __shared__ float Xs[BM][BK + 1];
    __shared__ float Wv[BN][BK + 1];
    __shared__ float Wm[BN][BK + 1];

    const int bm   = blockIdx.x >> 4;
    const int bn   = blockIdx.x & 15;
    const int row0 = bm * BM;
    const int n0   = bn * BN;

    const int tid = threadIdx.x;
    const int tx  = tid & 15;
    const int ty  = tid >> 4;
    const int rl  = ty * 2;
    const int nl  = tx * 2;

    const int lr = tid >> 3;
    const int lc = (tid & 7) * 4;

    float av[2][2] = {{0.f,0.f},{0.f,0.f}};
    float am[2][2] = {{0.f,0.f},{0.f,0.f}};

    for (int k0 = 0; k0 < NN; k0 += BK) {
        float4 xv = *reinterpret_cast<const float4*>(&x[(size_t)(row0 + lr) * NN + k0 + lc]);
        Xs[lr][lc + 0] = xv.x; Xs[lr][lc + 1] = xv.y;
        Xs[lr][lc + 2] = xv.z; Xs[lr][lc + 3] = xv.w;

        float4 wv = *reinterpret_cast<const float4*>(&W[(size_t)(n0 + lr) * NN + k0 + lc]);
        Wv[lr][lc + 0] = wv.x; Wv[lr][lc + 1] = wv.y;
        Wv[lr][lc + 2] = wv.z; Wv[lr][lc + 3] = wv.w;

        float4 wm = *reinterpret_cast<const float4*>(&W[(size_t)(512 + n0 + lr) * NN + k0 + lc]);
        Wm[lr][lc + 0] = wm.x; Wm[lr][lc + 1] = wm.y;
        Wm[lr][lc + 2] = wm.z; Wm[lr][lc + 3] = wm.w;

        __syncthreads();

        #pragma unroll
        for (int kk = 0; kk < BK; kk++) {
            float x0 = Xs[rl][kk],     x1 = Xs[rl + 1][kk];
            float v0 = Wv[nl][kk],     v1 = Wv[nl + 1][kk];
            float m0 = Wm[nl][kk],     m1 = Wm[nl + 1][kk];
            av[0][0] += x0 * v0;  av[0][1] += x0 * v1;
            av[1][0] += x1 * v0;  av[1][1] += x1 * v1;
            am[0][0] += x0 * m0;  am[0][1] += x0 * m1;
            am[1][0] += x1 * m0;  am[1][1] += x1 * m1;
        }
        __syncthreads();
    }

    #pragma unroll
    for (int rr = 0; rr < 2; rr++) {
        #pragma unroll
        for (int nn = 0; nn < 2; nn++) {
            const int row = row0 + rl + rr;
            const int n   = n0 + nl + nn;
            float v  = av[rr][nn] + b[n];
            float m  = am[rr][nn] + b[512 + n];
            float sp = (v > 20.f) ? v : log1pf(expf(v));   // softplus
            const int idx = row * NN + n;
            outM[idx] = m;
            outS[idx] = m + sqrtf(sp) * eps[idx];
            g_diag[idx] = sp;                              // stash diagonal (no race with fill)
        }
    }
}

// Scatter the softplus diagonal over the zeroed std_mat
__global__ __launch_bounds__(THREADS)
void diag_fixup(float* __restrict__ out)
{
    float* __restrict__ outD = out + 2 * SAMPLE_ELEMS;
    const unsigned i = blockIdx.x * THREADS + threadIdx.x;   // 0..131071
    outD[(size_t)i * NN + (i & 511u)] = g_diag[i];
}

extern "C" void kernel_launch(void* const* d_in, const int* in_sizes, int n_in,
                              void* d_out, int out_size)
{
    const float* x   = (const float*)d_in[0];   // (2,128,512)
    const float* W   = (const float*)d_in[1];   // (1024,512)
    const float* b   = (const float*)d_in[2];   // (1024,)
    const float* eps = (const float*)d_in[3];   // (2,128,512)
    float* out = (float*)d_out;

    (void)in_sizes; (void)n_in; (void)out_size;

    gaussian_sampler_main<<<NB_GEMM + NB_FILL, THREADS>>>(x, W, b, eps, out);
    diag_fixup<<<SAMPLE_ELEMS / THREADS, THREADS>>>(out);
}